// round 7
// baseline (speedup 1.0000x reference)
#include <cuda_runtime.h>
#include <math.h>
#include <stdint.h>

#define NN 100000
#define EE 1600000
#define DHID 256
#define DOUT 40
#define NB_SCAN ((NN + 1023) / 1024)

// ---------------- scratch (device globals; no allocation allowed) ----------------
__device__ int   g_outdeg[NN];
__device__ int   g_indeg[NN];
__device__ float g_isout[NN];
__device__ float g_isin[NN];
__device__ int   g_rowptr[NN + 1];
__device__ int   g_fill[NN];
__device__ int   g_bsum[NB_SCAN + 1];
__device__ int   g_cols[EE];
__device__ float g_z[(size_t)NN * DHID];   // GEMM output
__device__ float g_h[(size_t)NN * DHID];   // SpMM output / next-layer input

// ---------------- graph prep ----------------
__global__ void init_kernel() {
    int i = blockIdx.x * blockDim.x + threadIdx.x;
    if (i < NN) { g_outdeg[i] = 0; g_indeg[i] = 0; g_fill[i] = 0; }
}

__global__ void degree_kernel(const int* __restrict__ src, const int* __restrict__ dst) {
    int e = blockIdx.x * blockDim.x + threadIdx.x;
    if (e < EE) {
        atomicAdd(&g_outdeg[src[e]], 1);
        atomicAdd(&g_indeg[dst[e]], 1);
    }
}

// ---------- 3-phase exclusive scan of g_indeg -> g_rowptr ----------
__global__ void scan_partial_kernel() {
    __shared__ int ws[32];
    const int b = blockIdx.x, tid = threadIdx.x;
    const int i = b * 1024 + tid;
    int x = (i < NN) ? g_indeg[i] : 0;
    #pragma unroll
    for (int off = 16; off > 0; off >>= 1) x += __shfl_down_sync(0xffffffffu, x, off);
    if ((tid & 31) == 0) ws[tid >> 5] = x;
    __syncthreads();
    if (tid < 32) {
        int w = ws[tid];
        #pragma unroll
        for (int off = 16; off > 0; off >>= 1) w += __shfl_down_sync(0xffffffffu, w, off);
        if (tid == 0) g_bsum[b] = w;
    }
}

__global__ void scan_mid_kernel() {
    if (threadIdx.x == 0) {
        int run = 0;
        for (int b = 0; b < NB_SCAN; b++) { int t = g_bsum[b]; g_bsum[b] = run; run += t; }
        g_rowptr[NN] = run;
    }
}

// also computes isout/isin (folded former invsqrt_kernel)
__global__ void scan_final_kernel() {
    __shared__ int ws[32];
    const int b = blockIdx.x, tid = threadIdx.x;
    const int lane = tid & 31, wid = tid >> 5;
    const int i = b * 1024 + tid;
    const int v = (i < NN) ? g_indeg[i] : 0;
    int x = v;
    #pragma unroll
    for (int off = 1; off < 32; off <<= 1) {
        int y = __shfl_up_sync(0xffffffffu, x, off);
        if (lane >= off) x += y;
    }
    if (lane == 31) ws[wid] = x;
    __syncthreads();
    if (wid == 0) {
        int w = ws[lane];
        #pragma unroll
        for (int off = 1; off < 32; off <<= 1) {
            int y = __shfl_up_sync(0xffffffffu, w, off);
            if (lane >= off) w += y;
        }
        ws[lane] = w;
    }
    __syncthreads();
    int incl = x + ((wid > 0) ? ws[wid - 1] : 0);
    if (i < NN) {
        g_rowptr[i] = g_bsum[b] + incl - v;
        int od = g_outdeg[i];
        g_isout[i] = (od > 0) ? rsqrtf((float)od) : 0.f;
        g_isin[i]  = (v > 0) ? rsqrtf((float)v) : 0.f;
    }
}

__global__ void csr_fill_kernel(const int* __restrict__ src, const int* __restrict__ dst) {
    int e = blockIdx.x * blockDim.x + threadIdx.x;
    if (e < EE) {
        int d = dst[e];
        int p = g_rowptr[d] + atomicAdd(&g_fill[d], 1);
        g_cols[p] = src[e];
    }
}

// ---------------- GEMM: g_z[r,c] = sum_k (A[r,k]*isout[r]) * W[k,c] ----------------
// Tile 128x128, BK=16, 256 threads, 8x8/thread via packed f32x2 FMA.
// Bd stores duplicated (b,b) pairs SWIZZLED (pair p at slot (p&7)*16 + (p>>3)):
// thread tx reads its 8 pairs at slot j*16+tx -> conflict-free.
// Double-buffered: prefetch tile c+1 into registers during compute of tile c,
// one __syncthreads per iteration.
#define FMA2(d, a, b) asm("fma.rn.f32x2 %0, %1, %2, %0;" : "+l"(d) : "l"(a), "l"(b))

__global__ __launch_bounds__(256, 2)
void gemm_kernel(const float* __restrict__ Xin, int use_x,
                 const float* __restrict__ W, int nrows, int ncols)
{
    const float* __restrict__ A = use_x ? Xin : (const float*)g_h;
    __shared__ float As[2][16][128];                 // [buf][k][m]
    __shared__ unsigned long long BdS[2][16][128];   // [buf][k][swizzled pair slot]

    const int tid = threadIdx.x;
    const int tx = tid & 15, ty = tid >> 4;
    const int rowBase = blockIdx.x * 128;
    const int colBase = blockIdx.y * 128;

    // A loader: 2 threads/row, 8 consecutive k each
    const int lr = tid >> 1;
    const int lk = (tid & 1) * 8;
    const int arow = rowBase + lr;
    const float sc = (arow < nrows) ? g_isout[arow] : 0.f;
    const float4* Ar = (arow < nrows)
        ? reinterpret_cast<const float4*>(A + (size_t)arow * 256) : nullptr;

    // B loader: thread (bk, btx) loads 8 contiguous cols of row bk
    const int bk  = tid >> 4;
    const int btx = tid & 15;
    const int bc0 = colBase + btx * 8;
    const bool bfull = (bc0 + 7 < ncols);

    unsigned long long acc[4][8];
    #pragma unroll
    for (int i = 0; i < 4; i++)
        #pragma unroll
        for (int j = 0; j < 8; j++) acc[i][j] = 0ull;

    // ---- tile staging registers ----
    float4 a0, a1;
    float bv[8];

#define LDG_TILE(k0)                                                          \
    do {                                                                      \
        if (Ar) { a0 = Ar[((k0) + lk) >> 2]; a1 = Ar[((k0) + lk + 4) >> 2]; } \
        else    { a0 = make_float4(0.f,0.f,0.f,0.f); a1 = a0; }               \
        if (bfull) {                                                          \
            const float* Wr = &W[(size_t)((k0) + bk) * ncols + bc0];          \
            float4 w0 = *reinterpret_cast<const float4*>(Wr);                 \
            float4 w1 = *reinterpret_cast<const float4*>(Wr + 4);             \
            bv[0]=w0.x; bv[1]=w0.y; bv[2]=w0.z; bv[3]=w0.w;                   \
            bv[4]=w1.x; bv[5]=w1.y; bv[6]=w1.z; bv[7]=w1.w;                   \
        } else {                                                              \
            _Pragma("unroll")                                                 \
            for (int m = 0; m < 8; m++)                                       \
                bv[m] = (bc0 + m < ncols)                                     \
                    ? W[(size_t)((k0) + bk) * ncols + bc0 + m] : 0.f;         \
        }                                                                     \
    } while (0)

#define STS_TILE(buf)                                                         \
    do {                                                                      \
        As[buf][lk + 0][lr] = a0.x * sc; As[buf][lk + 1][lr] = a0.y * sc;     \
        As[buf][lk + 2][lr] = a0.z * sc; As[buf][lk + 3][lr] = a0.w * sc;     \
        As[buf][lk + 4][lr] = a1.x * sc; As[buf][lk + 5][lr] = a1.y * sc;     \
        As[buf][lk + 6][lr] = a1.z * sc; As[buf][lk + 7][lr] = a1.w * sc;     \
        _Pragma("unroll")                                                     \
        for (int m = 0; m < 8; m++) {                                         \
            unsigned int b_ = __float_as_uint(bv[m]);                         \
            BdS[buf][bk][m * 16 + btx] =                                      \
                ((unsigned long long)b_ << 32) | (unsigned long long)b_;      \
        }                                                                     \
    } while (0)

    // prologue: tile 0
    LDG_TILE(0);
    STS_TILE(0);
    __syncthreads();

    const int a_off = ty * 8;
    const int b_off = tx;

    for (int c = 0; c < 16; c++) {
        const int buf = c & 1;
        if (c < 15) LDG_TILE((c + 1) * 16);   // prefetch next tile (latency overlaps compute)

        #pragma unroll
        for (int kk = 0; kk < 16; kk++) {
            unsigned long long a2[4], bd[8];
            #pragma unroll
            for (int i = 0; i < 4; i++)
                a2[i] = *reinterpret_cast<const unsigned long long*>(&As[buf][kk][a_off + 2 * i]);
            #pragma unroll
            for (int j = 0; j < 8; j++)
                bd[j] = BdS[buf][kk][j * 16 + b_off];
            #pragma unroll
            for (int i = 0; i < 4; i++)
                #pragma unroll
                for (int j = 0; j < 8; j++)
                    FMA2(acc[i][j], a2[i], bd[j]);
        }

        if (c < 15) STS_TILE(1 - buf);
        __syncthreads();
    }

    // epilogue: acc[i][j] = (C[2i][j], C[2i+1][j]) rows ty*8+2i{,+1}, col tx*8+j
    const int c0 = colBase + tx * 8;
    #pragma unroll
    for (int i = 0; i < 4; i++) {
        #pragma unroll
        for (int h = 0; h < 2; h++) {
            int r = rowBase + ty * 8 + 2 * i + h;
            if (r >= nrows) continue;
            float vals[8];
            #pragma unroll
            for (int j = 0; j < 8; j++) {
                unsigned long long p = acc[i][j];
                unsigned int bits = h ? (unsigned int)(p >> 32) : (unsigned int)p;
                vals[j] = __uint_as_float(bits);
            }
            if (c0 + 7 < ncols) {
                float* zr = &g_z[(size_t)r * ncols + c0];
                *reinterpret_cast<float4*>(zr)     = make_float4(vals[0], vals[1], vals[2], vals[3]);
                *reinterpret_cast<float4*>(zr + 4) = make_float4(vals[4], vals[5], vals[6], vals[7]);
            } else {
                #pragma unroll
                for (int j = 0; j < 8; j++)
                    if (c0 + j < ncols) g_z[(size_t)r * ncols + c0 + j] = vals[j];
            }
        }
    }
}

// ---------------- SpMM gather (D=256): g_h[n] = relu(isin[n]*sum_e g_z[cols[e]] + b) ----------------
__global__ __launch_bounds__(256)
void spmm_kernel(const float* __restrict__ bias, int do_relu)
{
    __shared__ int scols[256];
    const int n = blockIdx.x;
    const int d = threadIdx.x;
    const int beg = g_rowptr[n];
    const int deg = g_rowptr[n + 1] - beg;
    float acc = 0.f;

    for (int base = 0; base < deg; base += 256) {
        const int m = min(256, deg - base);
        if (d < m) scols[d] = g_cols[beg + base + d];
        __syncthreads();
        int j = 0;
        for (; j + 8 <= m; j += 8) {
            float v0 = __ldg(&g_z[(size_t)scols[j + 0] * 256 + d]);
            float v1 = __ldg(&g_z[(size_t)scols[j + 1] * 256 + d]);
            float v2 = __ldg(&g_z[(size_t)scols[j + 2] * 256 + d]);
            float v3 = __ldg(&g_z[(size_t)scols[j + 3] * 256 + d]);
            float v4 = __ldg(&g_z[(size_t)scols[j + 4] * 256 + d]);
            float v5 = __ldg(&g_z[(size_t)scols[j + 5] * 256 + d]);
            float v6 = __ldg(&g_z[(size_t)scols[j + 6] * 256 + d]);
            float v7 = __ldg(&g_z[(size_t)scols[j + 7] * 256 + d]);
            acc += ((v0 + v1) + (v2 + v3)) + ((v4 + v5) + (v6 + v7));
        }
        for (; j < m; ++j)
            acc += __ldg(&g_z[(size_t)scols[j] * 256 + d]);
        __syncthreads();
    }

    float v = fmaf(acc, g_isin[n], bias[d]);
    g_h[(size_t)n * 256 + d] = do_relu ? fmaxf(v, 0.f) : v;
}

// ---------------- layer-3 SpMM (D=40) fused with log_softmax ----------------
__global__ __launch_bounds__(64)
void spmm_logsoftmax_kernel(const float* __restrict__ bias, float* __restrict__ out)
{
    const int n = blockIdx.x;
    const int d = threadIdx.x;   // 0..63, active d<40
    const int beg = g_rowptr[n];
    const int end = g_rowptr[n + 1];
    float acc = 0.f;
    if (d < DOUT) {
        int p = beg;
        for (; p + 4 <= end; p += 4) {
            float v0 = __ldg(&g_z[(size_t)__ldg(&g_cols[p + 0]) * DOUT + d]);
            float v1 = __ldg(&g_z[(size_t)__ldg(&g_cols[p + 1]) * DOUT + d]);
            float v2 = __ldg(&g_z[(size_t)__ldg(&g_cols[p + 2]) * DOUT + d]);
            float v3 = __ldg(&g_z[(size_t)__ldg(&g_cols[p + 3]) * DOUT + d]);
            acc += (v0 + v1) + (v2 + v3);
        }
        for (; p < end; ++p)
            acc += __ldg(&g_z[(size_t)__ldg(&g_cols[p]) * DOUT + d]);
    }
    float v = (d < DOUT) ? fmaf(acc, g_isin[n], bias[d]) : -INFINITY;

    __shared__ float sm[64];
    sm[d] = v;
    __syncthreads();
    #pragma unroll
    for (int off = 32; off > 0; off >>= 1) {
        if (d < off) sm[d] = fmaxf(sm[d], sm[d + off]);
        __syncthreads();
    }
    float mx = sm[0];
    __syncthreads();
    float ex = (d < DOUT) ? expf(v - mx) : 0.f;
    sm[d] = ex;
    __syncthreads();
    #pragma unroll
    for (int off = 32; off > 0; off >>= 1) {
        if (d < off) sm[d] += sm[d + off];
        __syncthreads();
    }
    float lse = mx + logf(sm[0]);
    if (d < DOUT) out[(size_t)n * DOUT + d] = v - lse;
}

// ---------------- launch ----------------
extern "C" void kernel_launch(void* const* d_in, const int* in_sizes, int n_in,
                              void* d_out, int out_size)
{
    const float* x  = (const float*)d_in[0];
    const float* W1 = (const float*)d_in[1];
    const float* b1 = (const float*)d_in[2];
    const float* W2 = (const float*)d_in[3];
    const float* b2 = (const float*)d_in[4];
    const float* W3 = (const float*)d_in[5];
    const float* b3 = (const float*)d_in[6];
    const int*  src = (const int*)d_in[7];
    const int*  dst = (const int*)d_in[8];
    float* out = (float*)d_out;

    const int nb_n = (NN + 255) / 256;
    const int nb_e = (EE + 255) / 256;

    // graph prep
    init_kernel<<<nb_n, 256>>>();
    degree_kernel<<<nb_e, 256>>>(src, dst);
    scan_partial_kernel<<<NB_SCAN, 1024>>>();
    scan_mid_kernel<<<1, 32>>>();
    scan_final_kernel<<<NB_SCAN, 1024>>>();   // also computes isout/isin
    csr_fill_kernel<<<nb_e, 256>>>(src, dst);

    // layer 1: z = (x*isout)@W1 ; h = relu(isin*gather(z) + b1)
    dim3 g256((NN + 127) / 128, 2);
    gemm_kernel<<<g256, 256>>>(x, 1, W1, NN, 256);
    spmm_kernel<<<NN, 256>>>(b1, 1);

    // layer 2
    gemm_kernel<<<g256, 256>>>(x, 0, W2, NN, 256);
    spmm_kernel<<<NN, 256>>>(b2, 1);

    // layer 3 (D_OUT=40) + log_softmax
    dim3 g40((NN + 127) / 128, 1);
    gemm_kernel<<<g40, 256>>>(x, 0, W3, NN, 40);
    spmm_logsoftmax_kernel<<<NN, 64>>>(b3, out);
}

// round 8
// speedup vs baseline: 1.0656x; 1.0656x over previous
#include <cuda_runtime.h>
#include <math.h>
#include <stdint.h>

#define NN 100000
#define EE 1600000
#define DHID 256
#define DOUT 40
#define NB_SCAN ((NN + 1023) / 1024)

// ---------------- scratch (device globals; zero-initialized at module load) ----------------
__device__ int   g_outdeg[NN];
__device__ int   g_indeg[NN];
__device__ float g_isout[NN];
__device__ float g_isin[NN];
__device__ int   g_rowptr[NN + 1];
__device__ int   g_fill[NN];
__device__ int   g_bsum[NB_SCAN + 1];
__device__ int   g_cols[EE];
__device__ float g_z[(size_t)NN * DHID];   // GEMM output
__device__ float g_h[(size_t)NN * DHID];   // SpMM output / next-layer input

// NOTE: counters (g_outdeg/g_indeg/g_fill) are zeroed AFTER their last use in
// each replay (scan_final / spmm), so every replay starts with them at 0 —
// including the first call, since __device__ globals are zero-initialized.

// ---------------- graph prep ----------------
__global__ void degree_kernel(const int* __restrict__ src, const int* __restrict__ dst) {
    int e = blockIdx.x * blockDim.x + threadIdx.x;
    if (e < EE) {
        atomicAdd(&g_outdeg[src[e]], 1);
        atomicAdd(&g_indeg[dst[e]], 1);
    }
}

// ---------- 3-phase exclusive scan of g_indeg -> g_rowptr ----------
__global__ void scan_partial_kernel() {
    __shared__ int ws[32];
    const int b = blockIdx.x, tid = threadIdx.x;
    const int i = b * 1024 + tid;
    int x = (i < NN) ? g_indeg[i] : 0;
    #pragma unroll
    for (int off = 16; off > 0; off >>= 1) x += __shfl_down_sync(0xffffffffu, x, off);
    if ((tid & 31) == 0) ws[tid >> 5] = x;
    __syncthreads();
    if (tid < 32) {
        int w = ws[tid];
        #pragma unroll
        for (int off = 16; off > 0; off >>= 1) w += __shfl_down_sync(0xffffffffu, w, off);
        if (tid == 0) g_bsum[b] = w;
    }
}

__global__ void scan_mid_kernel() {
    if (threadIdx.x == 0) {
        int run = 0;
        for (int b = 0; b < NB_SCAN; b++) { int t = g_bsum[b]; g_bsum[b] = run; run += t; }
        g_rowptr[NN] = run;
    }
}

// computes rowptr + isout/isin, then zeroes the degree counters for the next replay
__global__ void scan_final_kernel() {
    __shared__ int ws[32];
    const int b = blockIdx.x, tid = threadIdx.x;
    const int lane = tid & 31, wid = tid >> 5;
    const int i = b * 1024 + tid;
    const int v = (i < NN) ? g_indeg[i] : 0;
    int x = v;
    #pragma unroll
    for (int off = 1; off < 32; off <<= 1) {
        int y = __shfl_up_sync(0xffffffffu, x, off);
        if (lane >= off) x += y;
    }
    if (lane == 31) ws[wid] = x;
    __syncthreads();
    if (wid == 0) {
        int w = ws[lane];
        #pragma unroll
        for (int off = 1; off < 32; off <<= 1) {
            int y = __shfl_up_sync(0xffffffffu, w, off);
            if (lane >= off) w += y;
        }
        ws[lane] = w;
    }
    __syncthreads();
    int incl = x + ((wid > 0) ? ws[wid - 1] : 0);
    if (i < NN) {
        g_rowptr[i] = g_bsum[b] + incl - v;
        int od = g_outdeg[i];
        g_isout[i] = (od > 0) ? rsqrtf((float)od) : 0.f;
        g_isin[i]  = (v > 0) ? rsqrtf((float)v) : 0.f;
        g_indeg[i]  = 0;   // reset for next replay (last reader is this kernel)
        g_outdeg[i] = 0;
    }
}

__global__ void csr_fill_kernel(const int* __restrict__ src, const int* __restrict__ dst) {
    int e = blockIdx.x * blockDim.x + threadIdx.x;
    if (e < EE) {
        int d = dst[e];
        int p = g_rowptr[d] + atomicAdd(&g_fill[d], 1);
        g_cols[p] = src[e];
    }
}

// ---------------- GEMM: g_z[r,c] = sum_k (A[r,k]*isout[r]) * W[k,c] ----------------
// Tile 128x128, BK=16, 256 threads, 8x8/thread via packed f32x2 FMA.
// Bd stores duplicated (b,b) pairs SWIZZLED (pair p at slot (p&7)*16 + (p>>3)):
// thread tx reads its 8 pairs at slot j*16+tx -> conflict-free.
// Grid is (colBlocks, rowBlocks): column-blocks sharing A rows dispatch
// adjacently -> second A read hits L2.
#define FMA2(d, a, b) asm("fma.rn.f32x2 %0, %1, %2, %0;" : "+l"(d) : "l"(a), "l"(b))

__global__ __launch_bounds__(256, 2)
void gemm_kernel(const float* __restrict__ Xin, int use_x,
                 const float* __restrict__ W, int nrows, int ncols)
{
    const float* __restrict__ A = use_x ? Xin : (const float*)g_h;
    __shared__ float As[16][128];                 // [k][m]
    __shared__ unsigned long long BdS[16][128];   // [k][swizzled pair slot]

    const int tid = threadIdx.x;
    const int tx = tid & 15, ty = tid >> 4;
    const int rowBase = blockIdx.y * 128;
    const int colBase = blockIdx.x * 128;

    // A loader: 2 threads/row, 8 consecutive k each
    const int lr = tid >> 1;
    const int lk = (tid & 1) * 8;
    const int arow = rowBase + lr;
    const float sc = (arow < nrows) ? g_isout[arow] : 0.f;

    // B loader: thread (bk, btx) loads 8 contiguous cols of row bk
    const int bk  = tid >> 4;
    const int btx = tid & 15;
    const int bc0 = colBase + btx * 8;

    unsigned long long acc[4][8];
    #pragma unroll
    for (int i = 0; i < 4; i++)
        #pragma unroll
        for (int j = 0; j < 8; j++) acc[i][j] = 0ull;

    for (int k0 = 0; k0 < 256; k0 += 16) {
        // --- load A tile ---
        float4 a0 = make_float4(0.f, 0.f, 0.f, 0.f), a1 = a0;
        if (arow < nrows) {
            const float4* Ar = reinterpret_cast<const float4*>(A + (size_t)arow * 256);
            a0 = Ar[(k0 + lk) >> 2];
            a1 = Ar[(k0 + lk + 4) >> 2];
        }
        As[lk + 0][lr] = a0.x * sc; As[lk + 1][lr] = a0.y * sc;
        As[lk + 2][lr] = a0.z * sc; As[lk + 3][lr] = a0.w * sc;
        As[lk + 4][lr] = a1.x * sc; As[lk + 5][lr] = a1.y * sc;
        As[lk + 6][lr] = a1.z * sc; As[lk + 7][lr] = a1.w * sc;

        // --- load B tile (contiguous gmem, swizzled duplicated smem) ---
        float bv[8];
        if (bc0 + 7 < ncols) {
            const float* Wr = &W[(size_t)(k0 + bk) * ncols + bc0];
            float4 w0 = *reinterpret_cast<const float4*>(Wr);
            float4 w1 = *reinterpret_cast<const float4*>(Wr + 4);
            bv[0] = w0.x; bv[1] = w0.y; bv[2] = w0.z; bv[3] = w0.w;
            bv[4] = w1.x; bv[5] = w1.y; bv[6] = w1.z; bv[7] = w1.w;
        } else {
            #pragma unroll
            for (int m = 0; m < 8; m++)
                bv[m] = (bc0 + m < ncols) ? W[(size_t)(k0 + bk) * ncols + bc0 + m] : 0.f;
        }
        #pragma unroll
        for (int m = 0; m < 8; m++) {
            unsigned int b = __float_as_uint(bv[m]);
            unsigned long long pv = ((unsigned long long)b << 32) | (unsigned long long)b;
            BdS[bk][m * 16 + btx] = pv;
        }
        __syncthreads();

        #pragma unroll
        for (int kk = 0; kk < 16; kk++) {
            unsigned long long a2[4], bd[8];
            #pragma unroll
            for (int i = 0; i < 4; i++)
                a2[i] = *reinterpret_cast<const unsigned long long*>(&As[kk][ty * 8 + 2 * i]);
            #pragma unroll
            for (int j = 0; j < 8; j++)
                bd[j] = BdS[kk][j * 16 + tx];
            #pragma unroll
            for (int i = 0; i < 4; i++)
                #pragma unroll
                for (int j = 0; j < 8; j++)
                    FMA2(acc[i][j], a2[i], bd[j]);
        }
        __syncthreads();
    }

    // epilogue
    const int c0 = colBase + tx * 8;
    #pragma unroll
    for (int i = 0; i < 4; i++) {
        #pragma unroll
        for (int h = 0; h < 2; h++) {
            int r = rowBase + ty * 8 + 2 * i + h;
            if (r >= nrows) continue;
            float vals[8];
            #pragma unroll
            for (int j = 0; j < 8; j++) {
                unsigned long long p = acc[i][j];
                unsigned int bits = h ? (unsigned int)(p >> 32) : (unsigned int)p;
                vals[j] = __uint_as_float(bits);
            }
            if (c0 + 7 < ncols) {
                float* zr = &g_z[(size_t)r * ncols + c0];
                *reinterpret_cast<float4*>(zr)     = make_float4(vals[0], vals[1], vals[2], vals[3]);
                *reinterpret_cast<float4*>(zr + 4) = make_float4(vals[4], vals[5], vals[6], vals[7]);
            } else {
                #pragma unroll
                for (int j = 0; j < 8; j++)
                    if (c0 + j < ncols) g_z[(size_t)r * ncols + c0 + j] = vals[j];
            }
        }
    }
}

// ---------------- SpMM gather, feature-split: covers 128 of 256 dims per launch ----------------
// g_h[n, d] = relu(isin[n]*sum_e g_z[cols[e], d] + b[d]); d = half*128 + tid.
// Serializing the two halves keeps the gathered g_z working set at 51 MB (L2-resident).
__global__ __launch_bounds__(128)
void spmm_half_kernel(const float* __restrict__ bias, int half)
{
    __shared__ int scols[128];
    const int n = blockIdx.x;
    const int tid = threadIdx.x;
    const int d = half * 128 + tid;
    const int beg = g_rowptr[n];
    const int deg = g_rowptr[n + 1] - beg;
    if (tid == 0) g_fill[n] = 0;   // reset CSR fill counter for next replay (idempotent)
    float acc = 0.f;

    for (int base = 0; base < deg; base += 128) {
        const int m = min(128, deg - base);
        if (tid < m) scols[tid] = g_cols[beg + base + tid];
        __syncthreads();
        int j = 0;
        for (; j + 8 <= m; j += 8) {
            float v0 = __ldg(&g_z[(size_t)scols[j + 0] * 256 + d]);
            float v1 = __ldg(&g_z[(size_t)scols[j + 1] * 256 + d]);
            float v2 = __ldg(&g_z[(size_t)scols[j + 2] * 256 + d]);
            float v3 = __ldg(&g_z[(size_t)scols[j + 3] * 256 + d]);
            float v4 = __ldg(&g_z[(size_t)scols[j + 4] * 256 + d]);
            float v5 = __ldg(&g_z[(size_t)scols[j + 5] * 256 + d]);
            float v6 = __ldg(&g_z[(size_t)scols[j + 6] * 256 + d]);
            float v7 = __ldg(&g_z[(size_t)scols[j + 7] * 256 + d]);
            acc += ((v0 + v1) + (v2 + v3)) + ((v4 + v5) + (v6 + v7));
        }
        for (; j < m; ++j)
            acc += __ldg(&g_z[(size_t)scols[j] * 256 + d]);
        __syncthreads();
    }

    float v = fmaf(acc, g_isin[n], bias[d]);
    g_h[(size_t)n * 256 + d] = fmaxf(v, 0.f);
}

// ---------------- layer-3 SpMM (D=40) fused with log_softmax ----------------
__global__ __launch_bounds__(64)
void spmm_logsoftmax_kernel(const float* __restrict__ bias, float* __restrict__ out)
{
    const int n = blockIdx.x;
    const int d = threadIdx.x;   // 0..63, active d<40
    const int beg = g_rowptr[n];
    const int end = g_rowptr[n + 1];
    float acc = 0.f;
    if (d < DOUT) {
        int p = beg;
        for (; p + 4 <= end; p += 4) {
            float v0 = __ldg(&g_z[(size_t)__ldg(&g_cols[p + 0]) * DOUT + d]);
            float v1 = __ldg(&g_z[(size_t)__ldg(&g_cols[p + 1]) * DOUT + d]);
            float v2 = __ldg(&g_z[(size_t)__ldg(&g_cols[p + 2]) * DOUT + d]);
            float v3 = __ldg(&g_z[(size_t)__ldg(&g_cols[p + 3]) * DOUT + d]);
            acc += (v0 + v1) + (v2 + v3);
        }
        for (; p < end; ++p)
            acc += __ldg(&g_z[(size_t)__ldg(&g_cols[p]) * DOUT + d]);
    }
    float v = (d < DOUT) ? fmaf(acc, g_isin[n], bias[d]) : -INFINITY;

    __shared__ float sm[64];
    sm[d] = v;
    __syncthreads();
    #pragma unroll
    for (int off = 32; off > 0; off >>= 1) {
        if (d < off) sm[d] = fmaxf(sm[d], sm[d + off]);
        __syncthreads();
    }
    float mx = sm[0];
    __syncthreads();
    float ex = (d < DOUT) ? expf(v - mx) : 0.f;
    sm[d] = ex;
    __syncthreads();
    #pragma unroll
    for (int off = 32; off > 0; off >>= 1) {
        if (d < off) sm[d] += sm[d + off];
        __syncthreads();
    }
    float lse = mx + logf(sm[0]);
    if (d < DOUT) out[(size_t)n * DOUT + d] = v - lse;
}

// ---------------- launch ----------------
extern "C" void kernel_launch(void* const* d_in, const int* in_sizes, int n_in,
                              void* d_out, int out_size)
{
    const float* x  = (const float*)d_in[0];
    const float* W1 = (const float*)d_in[1];
    const float* b1 = (const float*)d_in[2];
    const float* W2 = (const float*)d_in[3];
    const float* b2 = (const float*)d_in[4];
    const float* W3 = (const float*)d_in[5];
    const float* b3 = (const float*)d_in[6];
    const int*  src = (const int*)d_in[7];
    const int*  dst = (const int*)d_in[8];
    float* out = (float*)d_out;

    const int nb_e = (EE + 255) / 256;

    // graph prep (counters are pre-zeroed: module load on first call,
    // end-of-replay resets afterwards)
    degree_kernel<<<nb_e, 256>>>(src, dst);
    scan_partial_kernel<<<NB_SCAN, 1024>>>();
    scan_mid_kernel<<<1, 32>>>();
    scan_final_kernel<<<NB_SCAN, 1024>>>();   // rowptr + isout/isin + counter reset
    csr_fill_kernel<<<nb_e, 256>>>(src, dst);

    const int gm = (NN + 127) / 128;

    // layer 1: z = (x*isout)@W1 ; h = relu(isin*gather(z) + b1)
    gemm_kernel<<<dim3(2, gm), 256>>>(x, 1, W1, NN, 256);
    spmm_half_kernel<<<NN, 128>>>(b1, 0);
    spmm_half_kernel<<<NN, 128>>>(b1, 1);

    // layer 2
    gemm_kernel<<<dim3(2, gm), 256>>>(x, 0, W2, NN, 256);
    spmm_half_kernel<<<NN, 128>>>(b2, 0);
    spmm_half_kernel<<<NN, 128>>>(b2, 1);

    // layer 3 (D_OUT=40) + log_softmax
    gemm_kernel<<<dim3(1, gm), 256>>>(x, 0, W3, NN, 40);
    spmm_logsoftmax_kernel<<<NN, 64>>>(b3, out);
}